// round 5
// baseline (speedup 1.0000x reference)
#include <cuda_runtime.h>
#include <cuda_bf16.h>
#include <cuda_fp8.h>
#include <math.h>

// ----- scratch (no allocations allowed) -----
#define NODE_CAP 131072
#define EDGE_CAP 4000000
#define SCAN_BLK 1024

__device__ float g_node_sum[NODE_CAP];   // per-node sum(exp(ell))
__device__ uint4 gQ8[NODE_CAP * 4];      // fp8 rows: 64B each
__device__ uint4 gK8[NODE_CAP * 4];
__device__ int g_hist[NODE_CAP];         // per-node edge counts
__device__ int g_start[NODE_CAP];        // exclusive offsets
__device__ int g_cursor[NODE_CAP];       // scatter cursors
__device__ int g_sorted_u[EDGE_CAP];     // u sorted by c
__device__ int g_blocksum[SCAN_BLK];     // scan partials
__device__ int g_blockoff[SCAN_BLK];

__global__ void zero_kernel(float* __restrict__ out, int num_graphs, int num_nodes) {
    int i = blockIdx.x * blockDim.x + threadIdx.x;
    if (i < num_nodes) g_hist[i] = 0;
    if (i < num_graphs) out[i] = 0.0f;
}

__device__ __forceinline__ unsigned pack4_fp8(float4 a) {
    unsigned short lo = __nv_cvt_float2_to_fp8x2(make_float2(a.x, a.y), __NV_SATFINITE, __NV_E4M3);
    unsigned short hi = __nv_cvt_float2_to_fp8x2(make_float2(a.z, a.w), __NV_SATFINITE, __NV_E4M3);
    return (unsigned)lo | ((unsigned)hi << 16);
}

__global__ void convert_kernel(const float4* __restrict__ Q,
                               const float4* __restrict__ K,
                               int total4 /* num_nodes*4 */) {
    int i = blockIdx.x * blockDim.x + threadIdx.x;
    if (i >= total4) return;
    uint4 o;
    {
        const float4* p = Q + i * 4;
        o.x = pack4_fp8(p[0]); o.y = pack4_fp8(p[1]);
        o.z = pack4_fp8(p[2]); o.w = pack4_fp8(p[3]);
        gQ8[i] = o;
    }
    {
        const float4* p = K + i * 4;
        o.x = pack4_fp8(p[0]); o.y = pack4_fp8(p[1]);
        o.z = pack4_fp8(p[2]); o.w = pack4_fp8(p[3]);
        gK8[i] = o;
    }
}

__global__ void hist_kernel(const int* __restrict__ c, int num_edges) {
    int e = blockIdx.x * blockDim.x + threadIdx.x;
    if (e < num_edges) atomicAdd(&g_hist[c[e]], 1);
}

// --- 3-phase exclusive scan over g_hist -> g_start ---
__global__ void scanA_kernel(int n) {
    __shared__ int sh[SCAN_BLK];
    int tid = threadIdx.x;
    int i = blockIdx.x * SCAN_BLK + tid;
    int v = (i < n) ? g_hist[i] : 0;
    sh[tid] = v;
    __syncthreads();
    for (int off = 1; off < SCAN_BLK; off <<= 1) {
        int t = (tid >= off) ? sh[tid - off] : 0;
        __syncthreads();
        sh[tid] += t;
        __syncthreads();
    }
    if (i < n) g_start[i] = sh[tid] - v;   // exclusive
    if (tid == SCAN_BLK - 1) g_blocksum[blockIdx.x] = sh[tid];
}

__global__ void scanB_kernel(int nblocks) {
    __shared__ int sh[SCAN_BLK];
    int tid = threadIdx.x;
    int v = (tid < nblocks) ? g_blocksum[tid] : 0;
    sh[tid] = v;
    __syncthreads();
    for (int off = 1; off < SCAN_BLK; off <<= 1) {
        int t = (tid >= off) ? sh[tid - off] : 0;
        __syncthreads();
        sh[tid] += t;
        __syncthreads();
    }
    if (tid < nblocks) g_blockoff[tid] = sh[tid] - v;  // exclusive block offsets
}

__global__ void scanC_kernel(int n) {
    int i = blockIdx.x * SCAN_BLK + threadIdx.x;
    if (i < n) {
        int s = g_start[i] + g_blockoff[blockIdx.x];
        g_start[i] = s;
        g_cursor[i] = s;
    }
}

__global__ void scatter_kernel(const int* __restrict__ c,
                               const int* __restrict__ u,
                               int num_edges) {
    int e = blockIdx.x * blockDim.x + threadIdx.x;
    if (e < num_edges) {
        int ci = c[e];
        int pos = atomicAdd(&g_cursor[ci], 1);
        g_sorted_u[pos] = u[e];
    }
}

__device__ __forceinline__ float dot_fp8_u4(uint4 q, uint4 k) {
    __half2 acc = __floats2half2_rn(0.0f, 0.0f);
    #pragma unroll
    for (int j = 0; j < 4; j++) {
        unsigned qw = (&q.x)[j];
        unsigned kw = (&k.x)[j];
        __half2_raw q0 = __nv_cvt_fp8x2_to_halfraw2((__nv_fp8x2_storage_t)(qw & 0xffffu), __NV_E4M3);
        __half2_raw q1 = __nv_cvt_fp8x2_to_halfraw2((__nv_fp8x2_storage_t)(qw >> 16),     __NV_E4M3);
        __half2_raw k0 = __nv_cvt_fp8x2_to_halfraw2((__nv_fp8x2_storage_t)(kw & 0xffffu), __NV_E4M3);
        __half2_raw k1 = __nv_cvt_fp8x2_to_halfraw2((__nv_fp8x2_storage_t)(kw >> 16),     __NV_E4M3);
        acc = __hfma2(*(__half2*)&q0, *(__half2*)&k0, acc);
        acc = __hfma2(*(__half2*)&q1, *(__half2*)&k1, acc);
    }
    float2 f = __half22float2(acc);
    return f.x + f.y;
}

// One warp per node. Q row loaded once per warp (lane li holds uint4 li of the row,
// replicated across 8 groups). Each iteration processes 16 edges: 8 groups x 2
// (manual 2x unroll for MLP). Trip count is warp-uniform -> all shuffles converged.
// Warp-total sum(exp) is written (no atomic) to g_node_sum[n].
__global__ void node_edge_kernel(int num_nodes) {
    const unsigned FULL = 0xffffffffu;
    int lane = threadIdx.x & 31;
    int li   = lane & 3;                 // lane within 4-lane group
    int grp  = lane >> 2;                // group within warp (0..7)
    int n = blockIdx.x * (blockDim.x >> 5) + (threadIdx.x >> 5);
    if (n >= num_nodes) return;          // warp-uniform exit

    uint4 q = gQ8[n * 4 + li];
    int start = g_start[n];
    int cnt   = g_hist[n];
    float acc = 0.0f;

    for (int j = 0; j < cnt; j += 16) {
        int e0 = j + grp;
        int e1 = j + 8 + grp;
        bool v0 = (e0 < cnt);
        bool v1 = (e1 < cnt);
        int u0 = v0 ? g_sorted_u[start + e0] : 0;
        int u1 = v1 ? g_sorted_u[start + e1] : 0;
        uint4 k0 = gK8[u0 * 4 + li];
        uint4 k1 = gK8[u1 * 4 + li];
        float d0 = dot_fp8_u4(q, k0);
        float d1 = dot_fp8_u4(q, k1);
        d0 += __shfl_xor_sync(FULL, d0, 1);
        d0 += __shfl_xor_sync(FULL, d0, 2);
        d1 += __shfl_xor_sync(FULL, d1, 1);
        d1 += __shfl_xor_sync(FULL, d1, 2);
        if (v0) acc += __expf(d0 * 0.125f);
        if (v1) acc += __expf(d1 * 0.125f);
    }

    // sum partial accs across the 8 groups (each group's lanes hold identical acc)
    acc += __shfl_xor_sync(FULL, acc, 4);
    acc += __shfl_xor_sync(FULL, acc, 8);
    acc += __shfl_xor_sync(FULL, acc, 16);

    if (lane == 0) g_node_sum[n] = acc;
}

// Per node: lse = log(sum) (0 for empty). batch is sorted -> warp-segmented
// reduction, only segment heads hit the per-graph atomic.
__global__ void node_kernel(const int* __restrict__ batch,
                            float* __restrict__ out,
                            int num_nodes) {
    const unsigned FULL = 0xffffffffu;
    int n = blockIdx.x * blockDim.x + threadIdx.x;
    int lane = threadIdx.x & 31;

    bool valid = (n < num_nodes);
    float v = 0.0f;
    int b = -1;
    if (valid) {
        float s = g_node_sum[n];
        v = (s > 0.0f) ? logf(s) : 0.0f;
        b = batch[n];
    }
    #pragma unroll
    for (int off = 1; off < 32; off <<= 1) {
        float ov = __shfl_down_sync(FULL, v, off);
        int   ob = __shfl_down_sync(FULL, b, off);
        if (lane + off < 32 && ob == b) v += ov;
    }
    int bprev = __shfl_up_sync(FULL, b, 1);
    bool head = (lane == 0) || (bprev != b);
    if (valid && head) {
        atomicAdd(&out[b], v);
    }
}

extern "C" void kernel_launch(void* const* d_in, const int* in_sizes, int n_in,
                              void* d_out, int out_size) {
    const float4* Q   = (const float4*)d_in[0];
    const float4* K   = (const float4*)d_in[1];
    const int* c      = (const int*)d_in[2];
    const int* u      = (const int*)d_in[3];
    const int* batch  = (const int*)d_in[4];

    int num_nodes  = in_sizes[0] / 64;
    int num_edges  = in_sizes[2];
    int num_graphs = out_size;
    float* out = (float*)d_out;

    int scan_blocks = (num_nodes + SCAN_BLK - 1) / SCAN_BLK;

    // zero hist + out
    {
        int n = num_nodes > num_graphs ? num_nodes : num_graphs;
        zero_kernel<<<(n + 255) / 256, 256>>>(out, num_graphs, num_nodes);
    }
    // fp32 -> fp8 conversion of Q and K
    {
        int total4 = num_nodes * 4;
        convert_kernel<<<(total4 + 255) / 256, 256>>>(Q, K, total4);
    }
    // histogram of destination nodes
    hist_kernel<<<(num_edges + 255) / 256, 256>>>(c, num_edges);
    // exclusive scan -> g_start, g_cursor
    scanA_kernel<<<scan_blocks, SCAN_BLK>>>(num_nodes);
    scanB_kernel<<<1, SCAN_BLK>>>(scan_blocks);
    scanC_kernel<<<scan_blocks, SCAN_BLK>>>(num_nodes);
    // scatter u into c-sorted order
    scatter_kernel<<<(num_edges + 255) / 256, 256>>>(c, u, num_edges);
    // per-node edge processing (warp per node)
    {
        int warps_per_block = 256 / 32;
        int blocks = (num_nodes + warps_per_block - 1) / warps_per_block;
        node_edge_kernel<<<blocks, 256>>>(num_nodes);
    }
    // per-node lse -> per-graph energy
    {
        int blocks = (num_nodes + 255) / 256;
        node_kernel<<<blocks, 256>>>(batch, out, num_nodes);
    }
}

// round 6
// speedup vs baseline: 2.2518x; 2.2518x over previous
#include <cuda_runtime.h>
#include <cuda_bf16.h>
#include <cuda_fp8.h>
#include <math.h>

// ----- scratch (no allocations allowed) -----
#define NODE_CAP 131072
__device__ float g_node_sum[NODE_CAP];
// fp8(e4m3) copies of Q,K: one row = 64 fp8 = 64 B = 4 uint4
__device__ uint4 gQ8[NODE_CAP * 4];
__device__ uint4 gK8[NODE_CAP * 4];

__device__ __forceinline__ unsigned pack4_fp8(float4 a) {
    unsigned short lo = __nv_cvt_float2_to_fp8x2(make_float2(a.x, a.y), __NV_SATFINITE, __NV_E4M3);
    unsigned short hi = __nv_cvt_float2_to_fp8x2(make_float2(a.z, a.w), __NV_SATFINITE, __NV_E4M3);
    return (unsigned)lo | ((unsigned)hi << 16);
}

// fp32 -> fp8 conversion (16 floats of Q and K per thread) fused with zeroing
// of g_node_sum and out. total4 = num_nodes*4 threads >= num_nodes >= num_graphs.
__global__ void convert_zero_kernel(const float4* __restrict__ Q,
                                    const float4* __restrict__ K,
                                    float* __restrict__ out,
                                    int total4, int num_nodes, int num_graphs) {
    int i = blockIdx.x * blockDim.x + threadIdx.x;
    if (i >= total4) return;
    if (i < num_nodes) g_node_sum[i] = 0.0f;
    if (i < num_graphs) out[i] = 0.0f;
    uint4 o;
    {
        const float4* p = Q + i * 4;
        o.x = pack4_fp8(p[0]); o.y = pack4_fp8(p[1]);
        o.z = pack4_fp8(p[2]); o.w = pack4_fp8(p[3]);
        gQ8[i] = o;
    }
    {
        const float4* p = K + i * 4;
        o.x = pack4_fp8(p[0]); o.y = pack4_fp8(p[1]);
        o.z = pack4_fp8(p[2]); o.w = pack4_fp8(p[3]);
        gK8[i] = o;
    }
}

__device__ __forceinline__ float dot_fp8_u4(uint4 q, uint4 k) {
    __half2 acc = __floats2half2_rn(0.0f, 0.0f);
    #pragma unroll
    for (int j = 0; j < 4; j++) {
        unsigned qw = (&q.x)[j];
        unsigned kw = (&k.x)[j];
        __half2_raw q0 = __nv_cvt_fp8x2_to_halfraw2((__nv_fp8x2_storage_t)(qw & 0xffffu), __NV_E4M3);
        __half2_raw q1 = __nv_cvt_fp8x2_to_halfraw2((__nv_fp8x2_storage_t)(qw >> 16),     __NV_E4M3);
        __half2_raw k0 = __nv_cvt_fp8x2_to_halfraw2((__nv_fp8x2_storage_t)(kw & 0xffffu), __NV_E4M3);
        __half2_raw k1 = __nv_cvt_fp8x2_to_halfraw2((__nv_fp8x2_storage_t)(kw >> 16),     __NV_E4M3);
        acc = __hfma2(*(__half2*)&q0, *(__half2*)&k0, acc);
        acc = __hfma2(*(__half2*)&q1, *(__half2*)&k1, acc);
    }
    float2 f = __half22float2(acc);
    return f.x + f.y;
}

// 4 lanes per edge, 2 edges per group slot -> 16 edges per warp.
// Each lane issues 4 independent uint4 loads (Q0,K0,Q1,K1) for MLP=4.
// Shuffles are single-shot and unconditional (all 32 lanes) -> no divergence hazard.
__global__ void edge_kernel(const int* __restrict__ c,
                            const int* __restrict__ u,
                            int num_edges) {
    const unsigned FULL = 0xffffffffu;
    int lane = threadIdx.x & 31;
    int grp  = lane >> 2;        // slot within warp (0..7)
    int li   = lane & 3;         // lane within 4-lane group
    int warp_id = (blockIdx.x * (blockDim.x >> 5)) + (threadIdx.x >> 5);
    int base = warp_id * 16;
    int e0 = base + grp;
    int e1 = base + 8 + grp;

    bool v0 = (e0 < num_edges);
    bool v1 = (e1 < num_edges);

    int c0 = 0, u0 = 0, c1 = 0, u1 = 0;
    if (v0) { c0 = c[e0]; u0 = u[e0]; }
    if (v1) { c1 = c[e1]; u1 = u[e1]; }

    float d0 = 0.0f, d1 = 0.0f;
    if (v0) {
        uint4 q = gQ8[c0 * 4 + li];
        uint4 k = gK8[u0 * 4 + li];
        d0 = dot_fp8_u4(q, k);
    }
    if (v1) {
        uint4 q = gQ8[c1 * 4 + li];
        uint4 k = gK8[u1 * 4 + li];
        d1 = dot_fp8_u4(q, k);
    }

    d0 += __shfl_xor_sync(FULL, d0, 1);
    d0 += __shfl_xor_sync(FULL, d0, 2);
    d1 += __shfl_xor_sync(FULL, d1, 1);
    d1 += __shfl_xor_sync(FULL, d1, 2);

    if (li == 0) {
        if (v0) atomicAdd(&g_node_sum[c0], __expf(d0 * 0.125f));
        if (v1) atomicAdd(&g_node_sum[c1], __expf(d1 * 0.125f));
    }
}

// Per node: lse = log(sum) (0 for empty). batch is sorted -> warp-segmented
// reduction, only segment heads hit the per-graph atomic.
__global__ void node_kernel(const int* __restrict__ batch,
                            float* __restrict__ out,
                            int num_nodes) {
    const unsigned FULL = 0xffffffffu;
    int n = blockIdx.x * blockDim.x + threadIdx.x;
    int lane = threadIdx.x & 31;

    bool valid = (n < num_nodes);
    float v = 0.0f;
    int b = -1;
    if (valid) {
        float s = g_node_sum[n];
        v = (s > 0.0f) ? logf(s) : 0.0f;
        b = batch[n];
    }
    #pragma unroll
    for (int off = 1; off < 32; off <<= 1) {
        float ov = __shfl_down_sync(FULL, v, off);
        int   ob = __shfl_down_sync(FULL, b, off);
        if (lane + off < 32 && ob == b) v += ov;
    }
    int bprev = __shfl_up_sync(FULL, b, 1);
    bool head = (lane == 0) || (bprev != b);
    if (valid && head) {
        atomicAdd(&out[b], v);
    }
}

extern "C" void kernel_launch(void* const* d_in, const int* in_sizes, int n_in,
                              void* d_out, int out_size) {
    const float4* Q   = (const float4*)d_in[0];
    const float4* K   = (const float4*)d_in[1];
    const int* c      = (const int*)d_in[2];
    const int* u      = (const int*)d_in[3];
    const int* batch  = (const int*)d_in[4];

    int num_nodes  = in_sizes[0] / 64;
    int num_edges  = in_sizes[2];
    int num_graphs = out_size;
    float* out = (float*)d_out;

    // fp32 -> fp8 conversion of Q and K, fused with zero of node_sum + out
    {
        int total4 = num_nodes * 4;
        convert_zero_kernel<<<(total4 + 255) / 256, 256>>>(Q, K, out, total4,
                                                           num_nodes, num_graphs);
    }
    // edges: 4 lanes per edge, 16 edges per warp (2 per slot for MLP)
    {
        int threads = 256;                         // 8 warps -> 128 edges per block
        int edges_per_block = (threads / 32) * 16;
        int blocks = (num_edges + edges_per_block - 1) / edges_per_block;
        edge_kernel<<<blocks, threads>>>(c, u, num_edges);
    }
    // nodes -> per-graph energy (warp-aggregated atomics)
    {
        int blocks = (num_nodes + 255) / 256;
        node_kernel<<<blocks, 256>>>(batch, out, num_nodes);
    }
}